// round 1
// baseline (speedup 1.0000x reference)
#include <cuda_runtime.h>
#include <cuda_bf16.h>
#include <math.h>

// Problem dims (fixed by reference)
#define BATCH 4
#define SEQ   2048
#define DMODEL 1024
#define NROWS (BATCH * SEQ)   // 8192

// ---------------- scratch (device globals; no allocation allowed) ----------------
__device__ float g_q[NROWS * DMODEL];
__device__ float g_k[NROWS * DMODEL];
__device__ float g_v[NROWS * DMODEL];
__device__ float g_p[BATCH * SEQ * SEQ];     // scores / attn
__device__ float g_ctx[NROWS * DMODEL];
__device__ float g_hid[NROWS * DMODEL];

// ---------------- SGEMM: C[M,N] = alpha * A[M,K] @ B ----------------
// TRANSB=false: B is row-major [K,N].  TRANSB=true: B is row-major [N,K] (C=A@B^T).
// Batched via blockIdx.z with element strides. 128x128 tile, BK=8, 256 thr, 8x8 micro.
template<bool TRANSB>
__global__ __launch_bounds__(256)
void sgemm_kernel(const float* __restrict__ A, const float* __restrict__ B,
                  float* __restrict__ C,
                  int M, int N, int K,
                  long batchA, long batchB, long batchC, float alpha)
{
    const int BM = 128, BN = 128, BK = 8;
    const long bz = blockIdx.z;
    A += bz * batchA; B += bz * batchB; C += bz * batchC;

    const int bm = blockIdx.y * BM;
    const int bn = blockIdx.x * BN;
    const int tid = threadIdx.x;

    __shared__ float As[BK][BM];
    __shared__ float Bs[BK][BN];

    float acc[8][8];
    #pragma unroll
    for (int i = 0; i < 8; i++)
        #pragma unroll
        for (int j = 0; j < 8; j++) acc[i][j] = 0.f;

    // A-tile load mapping: 128 rows x 8 cols; thread -> (row = tid>>1, col4 = (tid&1)*4)
    const int aRow = tid >> 1;
    const int aCol = (tid & 1) * 4;
    // B-tile (NN) mapping: 8 rows x 128 cols; thread -> (row = tid>>5, col4 = (tid&31)*4)
    const int bRow = tid >> 5;
    const int bCol = (tid & 31) * 4;

    const int tr = (tid >> 4) * 8;  // 0..120 step 8 (M dir)
    const int tc = (tid & 15) * 8;  // 0..120 step 8 (N dir)

    for (int kt = 0; kt < K; kt += BK) {
        float4 av = *reinterpret_cast<const float4*>(A + (long)(bm + aRow) * K + kt + aCol);
        As[aCol + 0][aRow] = av.x;
        As[aCol + 1][aRow] = av.y;
        As[aCol + 2][aRow] = av.z;
        As[aCol + 3][aRow] = av.w;
        if (TRANSB) {
            float4 bv = *reinterpret_cast<const float4*>(B + (long)(bn + aRow) * K + kt + aCol);
            Bs[aCol + 0][aRow] = bv.x;
            Bs[aCol + 1][aRow] = bv.y;
            Bs[aCol + 2][aRow] = bv.z;
            Bs[aCol + 3][aRow] = bv.w;
        } else {
            float4 bv = *reinterpret_cast<const float4*>(B + (long)(kt + bRow) * N + bn + bCol);
            *reinterpret_cast<float4*>(&Bs[bRow][bCol]) = bv;
        }
        __syncthreads();

        #pragma unroll
        for (int k = 0; k < BK; k++) {
            float ra[8], rb[8];
            *reinterpret_cast<float4*>(&ra[0]) = *reinterpret_cast<const float4*>(&As[k][tr]);
            *reinterpret_cast<float4*>(&ra[4]) = *reinterpret_cast<const float4*>(&As[k][tr + 4]);
            *reinterpret_cast<float4*>(&rb[0]) = *reinterpret_cast<const float4*>(&Bs[k][tc]);
            *reinterpret_cast<float4*>(&rb[4]) = *reinterpret_cast<const float4*>(&Bs[k][tc + 4]);
            #pragma unroll
            for (int i = 0; i < 8; i++)
                #pragma unroll
                for (int j = 0; j < 8; j++)
                    acc[i][j] = fmaf(ra[i], rb[j], acc[i][j]);
        }
        __syncthreads();
    }

    #pragma unroll
    for (int i = 0; i < 8; i++) {
        const long row = (long)(bm + tr + i) * N + bn + tc;
        float4 o0, o1;
        o0.x = alpha * acc[i][0]; o0.y = alpha * acc[i][1];
        o0.z = alpha * acc[i][2]; o0.w = alpha * acc[i][3];
        o1.x = alpha * acc[i][4]; o1.y = alpha * acc[i][5];
        o1.z = alpha * acc[i][6]; o1.w = alpha * acc[i][7];
        *reinterpret_cast<float4*>(C + row)     = o0;
        *reinterpret_cast<float4*>(C + row + 4) = o1;
    }
}

// ---------------- row softmax over SEQ=2048, one CTA (256 thr) per row ----------------
__global__ __launch_bounds__(256)
void softmax_kernel(float* __restrict__ p)
{
    __shared__ float sm[8];
    const long row = blockIdx.x;
    float* r = p + row * (long)SEQ;
    const int tid = threadIdx.x;

    float4 v0 = *reinterpret_cast<const float4*>(r + tid * 4);
    float4 v1 = *reinterpret_cast<const float4*>(r + 1024 + tid * 4);

    float m = fmaxf(fmaxf(fmaxf(v0.x, v0.y), fmaxf(v0.z, v0.w)),
                    fmaxf(fmaxf(v1.x, v1.y), fmaxf(v1.z, v1.w)));
    #pragma unroll
    for (int o = 16; o; o >>= 1) m = fmaxf(m, __shfl_xor_sync(0xffffffffu, m, o));
    if ((tid & 31) == 0) sm[tid >> 5] = m;
    __syncthreads();
    if (tid == 0) {
        float mm = sm[0];
        #pragma unroll
        for (int i = 1; i < 8; i++) mm = fmaxf(mm, sm[i]);
        sm[0] = mm;
    }
    __syncthreads();
    m = sm[0];
    __syncthreads();

    v0.x = __expf(v0.x - m); v0.y = __expf(v0.y - m);
    v0.z = __expf(v0.z - m); v0.w = __expf(v0.w - m);
    v1.x = __expf(v1.x - m); v1.y = __expf(v1.y - m);
    v1.z = __expf(v1.z - m); v1.w = __expf(v1.w - m);

    float s = v0.x + v0.y + v0.z + v0.w + v1.x + v1.y + v1.z + v1.w;
    #pragma unroll
    for (int o = 16; o; o >>= 1) s += __shfl_xor_sync(0xffffffffu, s, o);
    if ((tid & 31) == 0) sm[tid >> 5] = s;
    __syncthreads();
    if (tid == 0) {
        float ss = 0.f;
        #pragma unroll
        for (int i = 0; i < 8; i++) ss += sm[i];
        sm[0] = ss;
    }
    __syncthreads();
    const float inv = 1.0f / sm[0];

    v0.x *= inv; v0.y *= inv; v0.z *= inv; v0.w *= inv;
    v1.x *= inv; v1.y *= inv; v1.z *= inv; v1.w *= inv;
    *reinterpret_cast<float4*>(r + tid * 4) = v0;
    *reinterpret_cast<float4*>(r + 1024 + tid * 4) = v1;
}

// ---------------- LayerNorm over D=1024, one CTA (256 thr) per row ----------------
__global__ __launch_bounds__(256)
void layernorm_kernel(const float* __restrict__ h,
                      const float* __restrict__ gamma,
                      const float* __restrict__ beta,
                      float* __restrict__ out)
{
    __shared__ float sm[8];
    const long row = blockIdx.x;
    const int tid = threadIdx.x;
    const float* r = h + row * (long)DMODEL;

    float4 v = *reinterpret_cast<const float4*>(r + tid * 4);

    float s = v.x + v.y + v.z + v.w;
    #pragma unroll
    for (int o = 16; o; o >>= 1) s += __shfl_xor_sync(0xffffffffu, s, o);
    if ((tid & 31) == 0) sm[tid >> 5] = s;
    __syncthreads();
    if (tid == 0) {
        float ss = 0.f;
        #pragma unroll
        for (int i = 0; i < 8; i++) ss += sm[i];
        sm[0] = ss;
    }
    __syncthreads();
    const float mu = sm[0] * (1.0f / DMODEL);
    __syncthreads();

    float dx = v.x - mu, dy = v.y - mu, dz = v.z - mu, dw = v.w - mu;
    float sq = dx * dx + dy * dy + dz * dz + dw * dw;
    #pragma unroll
    for (int o = 16; o; o >>= 1) sq += __shfl_xor_sync(0xffffffffu, sq, o);
    if ((tid & 31) == 0) sm[tid >> 5] = sq;
    __syncthreads();
    if (tid == 0) {
        float ss = 0.f;
        #pragma unroll
        for (int i = 0; i < 8; i++) ss += sm[i];
        sm[0] = ss;
    }
    __syncthreads();
    const float rstd = rsqrtf(sm[0] * (1.0f / DMODEL) + 1e-5f);

    float4 g = *reinterpret_cast<const float4*>(gamma + tid * 4);
    float4 b = *reinterpret_cast<const float4*>(beta + tid * 4);
    float4 o;
    o.x = dx * rstd * g.x + b.x;
    o.y = dy * rstd * g.y + b.y;
    o.z = dz * rstd * g.z + b.z;
    o.w = dw * rstd * g.w + b.w;
    *reinterpret_cast<float4*>(out + row * (long)DMODEL + tid * 4) = o;
}

// ---------------- launch ----------------
extern "C" void kernel_launch(void* const* d_in, const int* in_sizes, int n_in,
                              void* d_out, int out_size)
{
    const float* x     = (const float*)d_in[0];
    const float* Wq    = (const float*)d_in[1];
    const float* Wk    = (const float*)d_in[2];
    const float* Wv    = (const float*)d_in[3];
    const float* Wo    = (const float*)d_in[4];
    const float* gamma = (const float*)d_in[5];
    const float* beta  = (const float*)d_in[6];
    float* out = (float*)d_out;

    float *q, *k, *v, *p, *ctx, *hid;
    cudaGetSymbolAddress((void**)&q,   g_q);
    cudaGetSymbolAddress((void**)&k,   g_k);
    cudaGetSymbolAddress((void**)&v,   g_v);
    cudaGetSymbolAddress((void**)&p,   g_p);
    cudaGetSymbolAddress((void**)&ctx, g_ctx);
    cudaGetSymbolAddress((void**)&hid, g_hid);

    const dim3 blk(256);

    // 1) Q, K, V projections: [8192,1024] @ [1024,1024]
    {
        dim3 grid(DMODEL / 128, NROWS / 128, 1);
        sgemm_kernel<false><<<grid, blk>>>(x, Wq, q, NROWS, DMODEL, DMODEL, 0, 0, 0, 1.0f);
        sgemm_kernel<false><<<grid, blk>>>(x, Wk, k, NROWS, DMODEL, DMODEL, 0, 0, 0, 1.0f);
        sgemm_kernel<false><<<grid, blk>>>(x, Wv, v, NROWS, DMODEL, DMODEL, 0, 0, 0, 1.0f);
    }

    // 2) scores = q @ k^T / sqrt(DK), batched over BATCH
    {
        dim3 grid(SEQ / 128, SEQ / 128, BATCH);
        const float alpha = 1.0f / 32.0f;  // 1/sqrt(1024)
        sgemm_kernel<true><<<grid, blk>>>(q, k, p, SEQ, SEQ, DMODEL,
                                          (long)SEQ * DMODEL, (long)SEQ * DMODEL,
                                          (long)SEQ * SEQ, alpha);
    }

    // 3) softmax rows
    softmax_kernel<<<BATCH * SEQ, blk>>>(p);

    // 4) ctx = attn @ v, batched
    {
        dim3 grid(DMODEL / 128, SEQ / 128, BATCH);
        sgemm_kernel<false><<<grid, blk>>>(p, v, ctx, SEQ, DMODEL, SEQ,
                                           (long)SEQ * SEQ, (long)SEQ * DMODEL,
                                           (long)SEQ * DMODEL, 1.0f);
    }

    // 5) hidden = ctx @ Wo
    {
        dim3 grid(DMODEL / 128, NROWS / 128, 1);
        sgemm_kernel<false><<<grid, blk>>>(ctx, Wo, hid, NROWS, DMODEL, DMODEL, 0, 0, 0, 1.0f);
    }

    // 6) layernorm -> out
    layernorm_kernel<<<NROWS, blk>>>(hid, gamma, beta, out);
}

// round 3
// speedup vs baseline: 3.2045x; 3.2045x over previous
#include <cuda_runtime.h>
#include <cuda_bf16.h>
#include <cstdint>
#include <math.h>

// ---------------------------------------------------------------- problem dims
#define BATCH 4
#define SEQ   2048
#define DMODEL 1024
#define NROWS (BATCH * SEQ)   // 8192

// ---------------------------------------------------------------- scratch
__device__ float g_xr [NROWS * DMODEL];      // x rounded to tf32
__device__ float g_q  [NROWS * DMODEL];
__device__ float g_k  [NROWS * DMODEL];
__device__ float g_v  [NROWS * DMODEL];
__device__ float g_vT [DMODEL * NROWS];      // [1024, 8192]
__device__ float g_p  [BATCH * SEQ * SEQ];   // scores / attn
__device__ float g_ctx[NROWS * DMODEL];
__device__ float g_hid[NROWS * DMODEL];
__device__ float g_wqT[DMODEL * DMODEL];
__device__ float g_wkT[DMODEL * DMODEL];
__device__ float g_wvT[DMODEL * DMODEL];
__device__ float g_woT[DMODEL * DMODEL];

// ---------------------------------------------------------------- helpers
__device__ __forceinline__ uint32_t smem_u32(const void* p) {
    uint32_t a;
    asm("{ .reg .u64 t; cvta.to.shared.u64 t, %1; cvt.u32.u64 %0, t; }" : "=r"(a) : "l"(p));
    return a;
}
__device__ __forceinline__ float round_tf32(float x) {
    float r;
    asm("cvt.rna.tf32.f32 %0, %1;" : "=f"(r) : "f"(x));
    return r;
}
__device__ __forceinline__ void cp_async16(uint32_t dst, const void* src) {
    asm volatile("cp.async.cg.shared.global [%0], [%1], 16;" :: "r"(dst), "l"(src) : "memory");
}
#define CP_COMMIT() asm volatile("cp.async.commit_group;" ::: "memory")
#define CP_WAIT2()  asm volatile("cp.async.wait_group 2;" ::: "memory")

__device__ __forceinline__ void ldsm_x4(uint32_t& r0, uint32_t& r1, uint32_t& r2, uint32_t& r3,
                                        uint32_t addr) {
    asm volatile("ldmatrix.sync.aligned.m8n8.x4.shared.b16 {%0,%1,%2,%3}, [%4];"
                 : "=r"(r0), "=r"(r1), "=r"(r2), "=r"(r3) : "r"(addr));
}
__device__ __forceinline__ void mma_tf32(float* d, uint32_t a0, uint32_t a1, uint32_t a2, uint32_t a3,
                                         uint32_t b0, uint32_t b1) {
    asm volatile("mma.sync.aligned.m16n8k8.row.col.f32.tf32.tf32.f32 "
                 "{%0,%1,%2,%3},{%4,%5,%6,%7},{%8,%9},{%0,%1,%2,%3};"
                 : "+f"(d[0]), "+f"(d[1]), "+f"(d[2]), "+f"(d[3])
                 : "r"(a0), "r"(a1), "r"(a2), "r"(a3), "r"(b0), "r"(b1));
}

// ---------------------------------------------------------------- GEMM
// C[M,N] = alpha * A[M,K] @ B[N,K]^T, both K-major. Tiles 128x128x16.
// smem: per stage, A = 128 rows x 80B (16 floats + 4 pad), B same. 4 stages.
#define ROW_B   80u            // bytes per smem row (20 floats)
#define HALF_B  10240u         // 128 * 80
#define STAGE_B 20480u
#define NSTAGE  4
#define GEMM_SMEM (NSTAGE * STAGE_B)   // 81920

template<bool ROUND>
__global__ __launch_bounds__(256, 1)
void gemm_mma_kernel(const float* __restrict__ A, const float* __restrict__ B,
                     float* __restrict__ C,
                     int K, int lda, int ldb, int ldc,
                     long bA, long bB, long bC, float alpha)
{
    extern __shared__ char smem[];
    const uint32_t sbase = smem_u32(smem);
    const int tid = threadIdx.x;
    const int wid = tid >> 5;
    const int lane = tid & 31;

    A += blockIdx.z * bA; B += blockIdx.z * bB; C += blockIdx.z * bC;
    const int bm = blockIdx.y * 128;
    const int bn = blockIdx.x * 128;
    const float* Ab = A + (long)bm * lda;
    const float* Bb = B + (long)bn * ldb;

    const int wm = (wid & 1) * 64;
    const int wn = (wid >> 1) * 32;

    float acc[4][4][4];
    #pragma unroll
    for (int i = 0; i < 4; i++)
        #pragma unroll
        for (int j = 0; j < 4; j++)
            #pragma unroll
            for (int f = 0; f < 4; f++) acc[i][j][f] = 0.f;

    // ldmatrix per-thread source coordinates
    const int ar = ((lane >> 3) & 1) * 8 + (lane & 7);   // A row within 16-row tile
    const int ac = lane >> 4;                            // A chunk offset (0/1)
    const int br = ((lane >> 4) & 1) * 8 + (lane & 7);   // B row within 16-row pair
    const int bc = (lane >> 3) & 1;                      // B chunk offset (0/1)

    // cp.async mapping: 512 16B chunks per half; thread does 2 per half
    const int r0c = tid >> 2,          ch0 = tid & 3;
    const int r1c = (tid + 256) >> 2,  ch1 = tid & 3;   // +256: row += 64, same chunk

    const int NK = K >> 4;

    #pragma unroll 1
    for (int s = 0; s < NSTAGE - 1; s++) {
        if (s < NK) {
            const int kt = s * 16;
            const uint32_t sa = sbase + (uint32_t)s * STAGE_B;
            const uint32_t sb = sa + HALF_B;
            cp_async16(sa + r0c * ROW_B + ch0 * 16u, Ab + (long)r0c * lda + kt + ch0 * 4);
            cp_async16(sa + r1c * ROW_B + ch1 * 16u, Ab + (long)r1c * lda + kt + ch1 * 4);
            cp_async16(sb + r0c * ROW_B + ch0 * 16u, Bb + (long)r0c * ldb + kt + ch0 * 4);
            cp_async16(sb + r1c * ROW_B + ch1 * 16u, Bb + (long)r1c * ldb + kt + ch1 * 4);
        }
        CP_COMMIT();
    }

    #pragma unroll 1
    for (int it = 0; it < NK; it++) {
        CP_WAIT2();
        __syncthreads();

        const uint32_t sa = sbase + (uint32_t)(it & (NSTAGE - 1)) * STAGE_B;
        const uint32_t sb = sa + HALF_B;

        #pragma unroll
        for (int ks = 0; ks < 2; ks++) {
            uint32_t a[4][4];
            #pragma unroll
            for (int mt = 0; mt < 4; mt++) {
                uint32_t addr = sa + (uint32_t)(wm + mt * 16 + ar) * ROW_B
                              + (uint32_t)(2 * ks + ac) * 16u;
                ldsm_x4(a[mt][0], a[mt][1], a[mt][2], a[mt][3], addr);
            }
            uint32_t b[4][2];
            #pragma unroll
            for (int nb = 0; nb < 2; nb++) {
                uint32_t t0, t1, t2, t3;
                uint32_t addr = sb + (uint32_t)(wn + nb * 16 + br) * ROW_B
                              + (uint32_t)(2 * ks + bc) * 16u;
                ldsm_x4(t0, t1, t2, t3, addr);
                b[2 * nb][0] = t0; b[2 * nb][1] = t1;
                b[2 * nb + 1][0] = t2; b[2 * nb + 1][1] = t3;
            }
            #pragma unroll
            for (int mt = 0; mt < 4; mt++)
                #pragma unroll
                for (int nt = 0; nt < 4; nt++)
                    mma_tf32(acc[mt][nt], a[mt][0], a[mt][1], a[mt][2], a[mt][3],
                             b[nt][0], b[nt][1]);
        }

        const int sn = it + NSTAGE - 1;
        if (sn < NK) {
            const int kt = sn * 16;
            const uint32_t sa2 = sbase + (uint32_t)(sn & (NSTAGE - 1)) * STAGE_B;
            const uint32_t sb2 = sa2 + HALF_B;
            cp_async16(sa2 + r0c * ROW_B + ch0 * 16u, Ab + (long)r0c * lda + kt + ch0 * 4);
            cp_async16(sa2 + r1c * ROW_B + ch1 * 16u, Ab + (long)r1c * lda + kt + ch1 * 4);
            cp_async16(sb2 + r0c * ROW_B + ch0 * 16u, Bb + (long)r0c * ldb + kt + ch0 * 4);
            cp_async16(sb2 + r1c * ROW_B + ch1 * 16u, Bb + (long)r1c * ldb + kt + ch1 * 4);
        }
        CP_COMMIT();
    }

    // epilogue: per-thread fragment rows/cols
    const int er = lane >> 2;
    const int ec = (lane & 3) * 2;
    #pragma unroll
    for (int mt = 0; mt < 4; mt++) {
        #pragma unroll
        for (int nt = 0; nt < 4; nt++) {
            const int row = bm + wm + mt * 16 + er;
            const int col = bn + wn + nt * 8 + ec;
            float2 lo, hi;
            lo.x = acc[mt][nt][0] * alpha; lo.y = acc[mt][nt][1] * alpha;
            hi.x = acc[mt][nt][2] * alpha; hi.y = acc[mt][nt][3] * alpha;
            if (ROUND) {
                lo.x = round_tf32(lo.x); lo.y = round_tf32(lo.y);
                hi.x = round_tf32(hi.x); hi.y = round_tf32(hi.y);
            }
            *reinterpret_cast<float2*>(C + (long)row * ldc + col) = lo;
            *reinterpret_cast<float2*>(C + (long)(row + 8) * ldc + col) = hi;
        }
    }
}

// ---------------------------------------------------------------- aux kernels
__global__ void copy_round_kernel(const float4* __restrict__ in, float4* __restrict__ out, int n4)
{
    int i = blockIdx.x * blockDim.x + threadIdx.x;
    if (i < n4) {
        float4 v = in[i];
        v.x = round_tf32(v.x); v.y = round_tf32(v.y);
        v.z = round_tf32(v.z); v.w = round_tf32(v.w);
        out[i] = v;
    }
}

// out[C,R] = round_tf32(in[R,C]^T)
__global__ void transpose_round_kernel(const float* __restrict__ in, float* __restrict__ out, int R, int C)
{
    __shared__ float t[32][33];
    const int cb = blockIdx.x * 32, rb = blockIdx.y * 32;
    const int x = threadIdx.x, y = threadIdx.y;   // 32 x 8
    #pragma unroll
    for (int i = 0; i < 32; i += 8)
        t[y + i][x] = in[(long)(rb + y + i) * C + cb + x];
    __syncthreads();
    #pragma unroll
    for (int i = 0; i < 32; i += 8)
        out[(long)(cb + y + i) * R + rb + x] = round_tf32(t[x][y + i]);
}

__global__ __launch_bounds__(256)
void softmax_kernel(float* __restrict__ p)
{
    __shared__ float sm[8];
    const long row = blockIdx.x;
    float* r = p + row * (long)SEQ;
    const int tid = threadIdx.x;

    float4 v0 = *reinterpret_cast<const float4*>(r + tid * 4);
    float4 v1 = *reinterpret_cast<const float4*>(r + 1024 + tid * 4);

    float m = fmaxf(fmaxf(fmaxf(v0.x, v0.y), fmaxf(v0.z, v0.w)),
                    fmaxf(fmaxf(v1.x, v1.y), fmaxf(v1.z, v1.w)));
    #pragma unroll
    for (int o = 16; o; o >>= 1) m = fmaxf(m, __shfl_xor_sync(0xffffffffu, m, o));
    if ((tid & 31) == 0) sm[tid >> 5] = m;
    __syncthreads();
    if (tid == 0) {
        float mm = sm[0];
        #pragma unroll
        for (int i = 1; i < 8; i++) mm = fmaxf(mm, sm[i]);
        sm[0] = mm;
    }
    __syncthreads();
    m = sm[0];
    __syncthreads();

    v0.x = __expf(v0.x - m); v0.y = __expf(v0.y - m);
    v0.z = __expf(v0.z - m); v0.w = __expf(v0.w - m);
    v1.x = __expf(v1.x - m); v1.y = __expf(v1.y - m);
    v1.z = __expf(v1.z - m); v1.w = __expf(v1.w - m);

    float s = v0.x + v0.y + v0.z + v0.w + v1.x + v1.y + v1.z + v1.w;
    #pragma unroll
    for (int o = 16; o; o >>= 1) s += __shfl_xor_sync(0xffffffffu, s, o);
    if ((tid & 31) == 0) sm[tid >> 5] = s;
    __syncthreads();
    if (tid == 0) {
        float ss = 0.f;
        #pragma unroll
        for (int i = 0; i < 8; i++) ss += sm[i];
        sm[0] = ss;
    }
    __syncthreads();
    const float inv = 1.0f / sm[0];

    v0.x = round_tf32(v0.x * inv); v0.y = round_tf32(v0.y * inv);
    v0.z = round_tf32(v0.z * inv); v0.w = round_tf32(v0.w * inv);
    v1.x = round_tf32(v1.x * inv); v1.y = round_tf32(v1.y * inv);
    v1.z = round_tf32(v1.z * inv); v1.w = round_tf32(v1.w * inv);
    *reinterpret_cast<float4*>(r + tid * 4) = v0;
    *reinterpret_cast<float4*>(r + 1024 + tid * 4) = v1;
}

__global__ __launch_bounds__(256)
void layernorm_kernel(const float* __restrict__ h,
                      const float* __restrict__ gamma,
                      const float* __restrict__ beta,
                      float* __restrict__ out)
{
    __shared__ float sm[8];
    const long row = blockIdx.x;
    const int tid = threadIdx.x;
    const float* r = h + row * (long)DMODEL;

    float4 v = *reinterpret_cast<const float4*>(r + tid * 4);

    float s = v.x + v.y + v.z + v.w;
    #pragma unroll
    for (int o = 16; o; o >>= 1) s += __shfl_xor_sync(0xffffffffu, s, o);
    if ((tid & 31) == 0) sm[tid >> 5] = s;
    __syncthreads();
    if (tid == 0) {
        float ss = 0.f;
        #pragma unroll
        for (int i = 0; i < 8; i++) ss += sm[i];
        sm[0] = ss;
    }
    __syncthreads();
    const float mu = sm[0] * (1.0f / DMODEL);
    __syncthreads();

    float dx = v.x - mu, dy = v.y - mu, dz = v.z - mu, dw = v.w - mu;
    float sq = dx * dx + dy * dy + dz * dz + dw * dw;
    #pragma unroll
    for (int o = 16; o; o >>= 1) sq += __shfl_xor_sync(0xffffffffu, sq, o);
    if ((tid & 31) == 0) sm[tid >> 5] = sq;
    __syncthreads();
    if (tid == 0) {
        float ss = 0.f;
        #pragma unroll
        for (int i = 0; i < 8; i++) ss += sm[i];
        sm[0] = ss;
    }
    __syncthreads();
    const float rstd = rsqrtf(sm[0] * (1.0f / DMODEL) + 1e-5f);

    float4 g = *reinterpret_cast<const float4*>(gamma + tid * 4);
    float4 b = *reinterpret_cast<const float4*>(beta + tid * 4);
    float4 o;
    o.x = dx * rstd * g.x + b.x;
    o.y = dy * rstd * g.y + b.y;
    o.z = dz * rstd * g.z + b.z;
    o.w = dw * rstd * g.w + b.w;
    *reinterpret_cast<float4*>(out + row * (long)DMODEL + tid * 4) = o;
}

// ---------------------------------------------------------------- launch
extern "C" void kernel_launch(void* const* d_in, const int* in_sizes, int n_in,
                              void* d_out, int out_size)
{
    const float* x     = (const float*)d_in[0];
    const float* Wq    = (const float*)d_in[1];
    const float* Wk    = (const float*)d_in[2];
    const float* Wv    = (const float*)d_in[3];
    const float* Wo    = (const float*)d_in[4];
    const float* gamma = (const float*)d_in[5];
    const float* beta  = (const float*)d_in[6];
    float* out = (float*)d_out;

    float *xr, *q, *k, *v, *vT, *p, *ctx, *hid, *wqT, *wkT, *wvT, *woT;
    cudaGetSymbolAddress((void**)&xr,  g_xr);
    cudaGetSymbolAddress((void**)&q,   g_q);
    cudaGetSymbolAddress((void**)&k,   g_k);
    cudaGetSymbolAddress((void**)&v,   g_v);
    cudaGetSymbolAddress((void**)&vT,  g_vT);
    cudaGetSymbolAddress((void**)&p,   g_p);
    cudaGetSymbolAddress((void**)&ctx, g_ctx);
    cudaGetSymbolAddress((void**)&hid, g_hid);
    cudaGetSymbolAddress((void**)&wqT, g_wqT);
    cudaGetSymbolAddress((void**)&wkT, g_wkT);
    cudaGetSymbolAddress((void**)&wvT, g_wvT);
    cudaGetSymbolAddress((void**)&woT, g_woT);

    static bool attr_done = false;
    cudaFuncSetAttribute(gemm_mma_kernel<false>, cudaFuncAttributeMaxDynamicSharedMemorySize, GEMM_SMEM);
    cudaFuncSetAttribute(gemm_mma_kernel<true>,  cudaFuncAttributeMaxDynamicSharedMemorySize, GEMM_SMEM);
    (void)attr_done;

    const dim3 blk(256);
    const dim3 tblk(32, 8);

    // 0) round x, transpose+round weights
    copy_round_kernel<<<(NROWS * DMODEL / 4 + 255) / 256, 256>>>((const float4*)x, (float4*)xr, NROWS * DMODEL / 4);
    {
        dim3 tg(DMODEL / 32, DMODEL / 32);
        transpose_round_kernel<<<tg, tblk>>>(Wq, wqT, DMODEL, DMODEL);
        transpose_round_kernel<<<tg, tblk>>>(Wk, wkT, DMODEL, DMODEL);
        transpose_round_kernel<<<tg, tblk>>>(Wv, wvT, DMODEL, DMODEL);
        transpose_round_kernel<<<tg, tblk>>>(Wo, woT, DMODEL, DMODEL);
    }

    // 1) projections: q/k rounded in epilogue (MMA operands of scores GEMM)
    {
        dim3 grid(DMODEL / 128, NROWS / 128, 1);
        gemm_mma_kernel<true ><<<grid, blk, GEMM_SMEM>>>(xr, wqT, q, DMODEL, DMODEL, DMODEL, DMODEL, 0, 0, 0, 1.0f);
        gemm_mma_kernel<true ><<<grid, blk, GEMM_SMEM>>>(xr, wkT, k, DMODEL, DMODEL, DMODEL, DMODEL, 0, 0, 0, 1.0f);
        gemm_mma_kernel<false><<<grid, blk, GEMM_SMEM>>>(xr, wvT, v, DMODEL, DMODEL, DMODEL, DMODEL, 0, 0, 0, 1.0f);
    }

    // 2) scores = q @ k^T / 32
    {
        dim3 grid(SEQ / 128, SEQ / 128, BATCH);
        gemm_mma_kernel<false><<<grid, blk, GEMM_SMEM>>>(q, k, p, DMODEL, DMODEL, DMODEL, SEQ,
                                                         (long)SEQ * DMODEL, (long)SEQ * DMODEL,
                                                         (long)SEQ * SEQ, 1.0f / 32.0f);
    }

    // 3) softmax (rounds attn to tf32)
    softmax_kernel<<<BATCH * SEQ, blk>>>(p);

    // 4) v^T (rounds), then ctx = attn @ v  (ctx rounded: it's the A-operand of out-proj)
    {
        dim3 tg(DMODEL / 32, NROWS / 32);
        transpose_round_kernel<<<tg, tblk>>>(v, vT, NROWS, DMODEL);
    }
    {
        dim3 grid(DMODEL / 128, SEQ / 128, BATCH);
        // batch b: B row n at vT + n*NROWS + b*SEQ -> ldb=NROWS, batch stride=SEQ
        gemm_mma_kernel<true><<<grid, blk, GEMM_SMEM>>>(p, vT, ctx, SEQ,
                                                        SEQ, NROWS, DMODEL,
                                                        (long)SEQ * SEQ, (long)SEQ,
                                                        (long)SEQ * DMODEL, 1.0f);
    }

    // 5) hidden = ctx @ Wo
    {
        dim3 grid(DMODEL / 128, NROWS / 128, 1);
        gemm_mma_kernel<false><<<grid, blk, GEMM_SMEM>>>(ctx, woT, hid, DMODEL, DMODEL, DMODEL, DMODEL, 0, 0, 0, 1.0f);
    }

    // 6) layernorm -> out
    layernorm_kernel<<<NROWS, blk>>>(hid, gamma, beta, out);
}

// round 4
// speedup vs baseline: 6.7385x; 2.1028x over previous
#include <cuda_runtime.h>
#include <cuda_fp16.h>
#include <cstdint>
#include <math.h>

// ---------------------------------------------------------------- problem dims
#define BATCH 4
#define SEQ   2048
#define DMODEL 1024
#define NROWS (BATCH * SEQ)   // 8192

// ---------------------------------------------------------------- scratch
__device__ __half g_xh  [NROWS * DMODEL];
__device__ __half g_qh  [NROWS * DMODEL];
__device__ __half g_kh  [NROWS * DMODEL];
__device__ __half g_vh  [NROWS * DMODEL];
__device__ __half g_vTh [DMODEL * NROWS];
__device__ float  g_s   [BATCH * SEQ * SEQ];   // fp32 scores
__device__ __half g_ph  [BATCH * SEQ * SEQ];   // fp16 probs
__device__ __half g_ctxh[NROWS * DMODEL];
__device__ float  g_hid [NROWS * DMODEL];
__device__ __half g_wqT [DMODEL * DMODEL];
__device__ __half g_wkT [DMODEL * DMODEL];
__device__ __half g_wvT [DMODEL * DMODEL];
__device__ __half g_woT [DMODEL * DMODEL];

// ---------------------------------------------------------------- helpers
__device__ __forceinline__ uint32_t smem_u32(const void* p) {
    uint32_t a;
    asm("{ .reg .u64 t; cvta.to.shared.u64 t, %1; cvt.u32.u64 %0, t; }" : "=r"(a) : "l"(p));
    return a;
}
__device__ __forceinline__ void cp_async16(uint32_t dst, const void* src) {
    asm volatile("cp.async.cg.shared.global [%0], [%1], 16;" :: "r"(dst), "l"(src) : "memory");
}
#define CP_COMMIT() asm volatile("cp.async.commit_group;" ::: "memory")
#define CP_WAIT2()  asm volatile("cp.async.wait_group 2;" ::: "memory")

__device__ __forceinline__ void ldsm_x4(uint32_t& r0, uint32_t& r1, uint32_t& r2, uint32_t& r3,
                                        uint32_t addr) {
    asm volatile("ldmatrix.sync.aligned.m8n8.x4.shared.b16 {%0,%1,%2,%3}, [%4];"
                 : "=r"(r0), "=r"(r1), "=r"(r2), "=r"(r3) : "r"(addr));
}
// m16n8k16 fp16 inputs, fp32 accumulate
__device__ __forceinline__ void mma_f16(float* d, uint32_t a0, uint32_t a1, uint32_t a2, uint32_t a3,
                                        uint32_t b0, uint32_t b1) {
    asm volatile("mma.sync.aligned.m16n8k16.row.col.f32.f16.f16.f32 "
                 "{%0,%1,%2,%3},{%4,%5,%6,%7},{%8,%9},{%0,%1,%2,%3};"
                 : "+f"(d[0]), "+f"(d[1]), "+f"(d[2]), "+f"(d[3])
                 : "r"(a0), "r"(a1), "r"(a2), "r"(a3), "r"(b0), "r"(b1));
}

// ---------------------------------------------------------------- GEMM
// C[M,N] = alpha * A[M,K] @ B[N,K]^T, A,B fp16 K-major. Tile 128x128x32.
// smem row: 64B payload (32 fp16) + 16B pad = 80B stride -> conflict-free ldmatrix.
#define ROW_B   80u
#define HALF_B  10240u         // 128 * 80
#define STAGE_B 20480u
#define NSTAGE  4
#define GEMM_SMEM (NSTAGE * STAGE_B)   // 81920

template<typename OT>
__global__ __launch_bounds__(256, 2)
void gemm_h_kernel(const __half* __restrict__ A, const __half* __restrict__ B,
                   OT* __restrict__ C,
                   int K, int lda, int ldb, int ldc,
                   long bA, long bB, long bC, float alpha)
{
    extern __shared__ char smem[];
    const uint32_t sbase = smem_u32(smem);
    const int tid = threadIdx.x;
    const int wid = tid >> 5;
    const int lane = tid & 31;

    A += blockIdx.z * bA; B += blockIdx.z * bB; C += blockIdx.z * bC;
    const int bm = blockIdx.y * 128;
    const int bn = blockIdx.x * 128;
    const __half* Ab = A + (long)bm * lda;
    const __half* Bb = B + (long)bn * ldb;

    const int wm = (wid & 1) * 64;
    const int wn = (wid >> 1) * 32;

    float acc[4][4][4];
    #pragma unroll
    for (int i = 0; i < 4; i++)
        #pragma unroll
        for (int j = 0; j < 4; j++)
            #pragma unroll
            for (int f = 0; f < 4; f++) acc[i][j][f] = 0.f;

    // ldmatrix per-lane address components
    const uint32_t a_row = (uint32_t)(wm + (lane & 15));
    const uint32_t a_col = (uint32_t)((lane >> 4) * 16);
    const uint32_t b_row = (uint32_t)(wn + (lane & 7) + ((lane >> 4) & 1) * 8);
    const uint32_t b_col = (uint32_t)(((lane >> 3) & 1) * 16);

    // cp.async mapping: 512 chunks (16B) per operand per stage; 2 per thread per operand
    const int r0c = tid >> 2,  j0 = tid & 3;
    const int r1c = r0c + 64,  j1 = tid & 3;

    const int NK = K >> 5;

    #pragma unroll 1
    for (int s = 0; s < NSTAGE - 1; s++) {
        if (s < NK) {
            const int kt = s * 32;
            const uint32_t sa = sbase + (uint32_t)s * STAGE_B;
            const uint32_t sb = sa + HALF_B;
            cp_async16(sa + r0c * ROW_B + j0 * 16u, Ab + (long)r0c * lda + kt + j0 * 8);
            cp_async16(sa + r1c * ROW_B + j1 * 16u, Ab + (long)r1c * lda + kt + j1 * 8);
            cp_async16(sb + r0c * ROW_B + j0 * 16u, Bb + (long)r0c * ldb + kt + j0 * 8);
            cp_async16(sb + r1c * ROW_B + j1 * 16u, Bb + (long)r1c * ldb + kt + j1 * 8);
        }
        CP_COMMIT();
    }

    #pragma unroll 1
    for (int it = 0; it < NK; it++) {
        CP_WAIT2();
        __syncthreads();

        const uint32_t sa = sbase + (uint32_t)(it & (NSTAGE - 1)) * STAGE_B;
        const uint32_t sb = sa + HALF_B;

        #pragma unroll
        for (int ks = 0; ks < 2; ks++) {
            uint32_t a[4][4];
            #pragma unroll
            for (int mt = 0; mt < 4; mt++) {
                uint32_t addr = sa + (a_row + (uint32_t)(mt * 16)) * ROW_B
                              + a_col + (uint32_t)(ks * 32);
                ldsm_x4(a[mt][0], a[mt][1], a[mt][2], a[mt][3], addr);
            }
            uint32_t b[4][2];
            #pragma unroll
            for (int nb = 0; nb < 2; nb++) {
                uint32_t t0, t1, t2, t3;
                uint32_t addr = sb + (b_row + (uint32_t)(nb * 16)) * ROW_B
                              + b_col + (uint32_t)(ks * 32);
                ldsm_x4(t0, t1, t2, t3, addr);
                b[2 * nb][0] = t0; b[2 * nb][1] = t1;
                b[2 * nb + 1][0] = t2; b[2 * nb + 1][1] = t3;
            }
            #pragma unroll
            for (int mt = 0; mt < 4; mt++)
                #pragma unroll
                for (int nt = 0; nt < 4; nt++)
                    mma_f16(acc[mt][nt], a[mt][0], a[mt][1], a[mt][2], a[mt][3],
                            b[nt][0], b[nt][1]);
        }

        const int sn = it + NSTAGE - 1;
        if (sn < NK) {
            const int kt = sn * 32;
            const uint32_t sa2 = sbase + (uint32_t)(sn & (NSTAGE - 1)) * STAGE_B;
            const uint32_t sb2 = sa2 + HALF_B;
            cp_async16(sa2 + r0c * ROW_B + j0 * 16u, Ab + (long)r0c * lda + kt + j0 * 8);
            cp_async16(sa2 + r1c * ROW_B + j1 * 16u, Ab + (long)r1c * lda + kt + j1 * 8);
            cp_async16(sb2 + r0c * ROW_B + j0 * 16u, Bb + (long)r0c * ldb + kt + j0 * 8);
            cp_async16(sb2 + r1c * ROW_B + j1 * 16u, Bb + (long)r1c * ldb + kt + j1 * 8);
        }
        CP_COMMIT();
    }

    // epilogue
    const int er = lane >> 2;
    const int ec = (lane & 3) * 2;
    #pragma unroll
    for (int mt = 0; mt < 4; mt++) {
        #pragma unroll
        for (int nt = 0; nt < 4; nt++) {
            const int row = bm + wm + mt * 16 + er;
            const int col = bn + wn + nt * 8 + ec;
            float v0 = acc[mt][nt][0] * alpha, v1 = acc[mt][nt][1] * alpha;
            float v2 = acc[mt][nt][2] * alpha, v3 = acc[mt][nt][3] * alpha;
            if constexpr (sizeof(OT) == 2) {
                *reinterpret_cast<__half2*>((__half*)C + (long)row * ldc + col) =
                    __floats2half2_rn(v0, v1);
                *reinterpret_cast<__half2*>((__half*)C + (long)(row + 8) * ldc + col) =
                    __floats2half2_rn(v2, v3);
            } else {
                *reinterpret_cast<float2*>((float*)C + (long)row * ldc + col) =
                    make_float2(v0, v1);
                *reinterpret_cast<float2*>((float*)C + (long)(row + 8) * ldc + col) =
                    make_float2(v2, v3);
            }
        }
    }
}

// ---------------------------------------------------------------- aux kernels
__global__ void convert_f32_f16_kernel(const float4* __restrict__ in, uint2* __restrict__ out, int n4)
{
    int i = blockIdx.x * blockDim.x + threadIdx.x;
    if (i < n4) {
        float4 v = in[i];
        __half2 lo = __floats2half2_rn(v.x, v.y);
        __half2 hi = __floats2half2_rn(v.z, v.w);
        uint2 o;
        o.x = *reinterpret_cast<uint32_t*>(&lo);
        o.y = *reinterpret_cast<uint32_t*>(&hi);
        out[i] = o;
    }
}

// out[C,R] (fp16) = in[R,C]^T (fp32)
__global__ void transpose_w_kernel(const float* __restrict__ in, __half* __restrict__ out, int R, int C)
{
    __shared__ float t[32][33];
    const int cb = blockIdx.x * 32, rb = blockIdx.y * 32;
    const int x = threadIdx.x, y = threadIdx.y;   // 32 x 8
    #pragma unroll
    for (int i = 0; i < 32; i += 8)
        t[y + i][x] = in[(long)(rb + y + i) * C + cb + x];
    __syncthreads();
    #pragma unroll
    for (int i = 0; i < 32; i += 8)
        out[(long)(cb + y + i) * R + rb + x] = __float2half(t[x][y + i]);
}

// out[C,R] (fp16) = in[R,C]^T (fp16)
__global__ void transpose_h_kernel(const __half* __restrict__ in, __half* __restrict__ out, int R, int C)
{
    __shared__ __half t[32][34];
    const int cb = blockIdx.x * 32, rb = blockIdx.y * 32;
    const int x = threadIdx.x, y = threadIdx.y;   // 32 x 8
    #pragma unroll
    for (int i = 0; i < 32; i += 8)
        t[y + i][x] = in[(long)(rb + y + i) * C + cb + x];
    __syncthreads();
    #pragma unroll
    for (int i = 0; i < 32; i += 8)
        out[(long)(cb + y + i) * R + rb + x] = t[x][y + i];
}

// softmax over rows of 2048 fp32 scores -> fp16 probs
__global__ __launch_bounds__(256)
void softmax_kernel(const float* __restrict__ s, __half* __restrict__ p)
{
    __shared__ float sm[8];
    const long row = blockIdx.x;
    const float* r = s + row * (long)SEQ;
    __half* o = p + row * (long)SEQ;
    const int tid = threadIdx.x;

    float4 v0 = *reinterpret_cast<const float4*>(r + tid * 4);
    float4 v1 = *reinterpret_cast<const float4*>(r + 1024 + tid * 4);

    float m = fmaxf(fmaxf(fmaxf(v0.x, v0.y), fmaxf(v0.z, v0.w)),
                    fmaxf(fmaxf(v1.x, v1.y), fmaxf(v1.z, v1.w)));
    #pragma unroll
    for (int of = 16; of; of >>= 1) m = fmaxf(m, __shfl_xor_sync(0xffffffffu, m, of));
    if ((tid & 31) == 0) sm[tid >> 5] = m;
    __syncthreads();
    if (tid == 0) {
        float mm = sm[0];
        #pragma unroll
        for (int i = 1; i < 8; i++) mm = fmaxf(mm, sm[i]);
        sm[0] = mm;
    }
    __syncthreads();
    m = sm[0];
    __syncthreads();

    v0.x = __expf(v0.x - m); v0.y = __expf(v0.y - m);
    v0.z = __expf(v0.z - m); v0.w = __expf(v0.w - m);
    v1.x = __expf(v1.x - m); v1.y = __expf(v1.y - m);
    v1.z = __expf(v1.z - m); v1.w = __expf(v1.w - m);

    float su = v0.x + v0.y + v0.z + v0.w + v1.x + v1.y + v1.z + v1.w;
    #pragma unroll
    for (int of = 16; of; of >>= 1) su += __shfl_xor_sync(0xffffffffu, su, of);
    if ((tid & 31) == 0) sm[tid >> 5] = su;
    __syncthreads();
    if (tid == 0) {
        float ss = 0.f;
        #pragma unroll
        for (int i = 0; i < 8; i++) ss += sm[i];
        sm[0] = ss;
    }
    __syncthreads();
    const float inv = 1.0f / sm[0];

    __half2 h0 = __floats2half2_rn(v0.x * inv, v0.y * inv);
    __half2 h1 = __floats2half2_rn(v0.z * inv, v0.w * inv);
    __half2 h2 = __floats2half2_rn(v1.x * inv, v1.y * inv);
    __half2 h3 = __floats2half2_rn(v1.z * inv, v1.w * inv);
    *reinterpret_cast<__half2*>(o + tid * 4)        = h0;
    *reinterpret_cast<__half2*>(o + tid * 4 + 2)    = h1;
    *reinterpret_cast<__half2*>(o + 1024 + tid * 4)     = h2;
    *reinterpret_cast<__half2*>(o + 1024 + tid * 4 + 2) = h3;
}

__global__ __launch_bounds__(256)
void layernorm_kernel(const float* __restrict__ h,
                      const float* __restrict__ gamma,
                      const float* __restrict__ beta,
                      float* __restrict__ out)
{
    __shared__ float sm[8];
    const long row = blockIdx.x;
    const int tid = threadIdx.x;
    const float* r = h + row * (long)DMODEL;

    float4 v = *reinterpret_cast<const float4*>(r + tid * 4);

    float s = v.x + v.y + v.z + v.w;
    #pragma unroll
    for (int o = 16; o; o >>= 1) s += __shfl_xor_sync(0xffffffffu, s, o);
    if ((tid & 31) == 0) sm[tid >> 5] = s;
    __syncthreads();
    if (tid == 0) {
        float ss = 0.f;
        #pragma unroll
        for (int i = 0; i < 8; i++) ss += sm[i];
        sm[0] = ss;
    }
    __syncthreads();
    const float mu = sm[0] * (1.0f / DMODEL);
    __syncthreads();

    float dx = v.x - mu, dy = v.y - mu, dz = v.z - mu, dw = v.w - mu;
    float sq = dx * dx + dy * dy + dz * dz + dw * dw;
    #pragma unroll
    for (int o = 16; o; o >>= 1) sq += __shfl_xor_sync(0xffffffffu, sq, o);
    if ((tid & 31) == 0) sm[tid >> 5] = sq;
    __syncthreads();
    if (tid == 0) {
        float ss = 0.f;
        #pragma unroll
        for (int i = 0; i < 8; i++) ss += sm[i];
        sm[0] = ss;
    }
    __syncthreads();
    const float rstd = rsqrtf(sm[0] * (1.0f / DMODEL) + 1e-5f);

    float4 g = *reinterpret_cast<const float4*>(gamma + tid * 4);
    float4 b = *reinterpret_cast<const float4*>(beta + tid * 4);
    float4 o;
    o.x = dx * rstd * g.x + b.x;
    o.y = dy * rstd * g.y + b.y;
    o.z = dz * rstd * g.z + b.z;
    o.w = dw * rstd * g.w + b.w;
    *reinterpret_cast<float4*>(out + row * (long)DMODEL + tid * 4) = o;
}

// ---------------------------------------------------------------- launch
extern "C" void kernel_launch(void* const* d_in, const int* in_sizes, int n_in,
                              void* d_out, int out_size)
{
    const float* x     = (const float*)d_in[0];
    const float* Wq    = (const float*)d_in[1];
    const float* Wk    = (const float*)d_in[2];
    const float* Wv    = (const float*)d_in[3];
    const float* Wo    = (const float*)d_in[4];
    const float* gamma = (const float*)d_in[5];
    const float* beta  = (const float*)d_in[6];
    float* out = (float*)d_out;

    __half *xh, *qh, *kh, *vh, *vTh, *ph, *ctxh, *wqT, *wkT, *wvT, *woT;
    float *s, *hid;
    cudaGetSymbolAddress((void**)&xh,   g_xh);
    cudaGetSymbolAddress((void**)&qh,   g_qh);
    cudaGetSymbolAddress((void**)&kh,   g_kh);
    cudaGetSymbolAddress((void**)&vh,   g_vh);
    cudaGetSymbolAddress((void**)&vTh,  g_vTh);
    cudaGetSymbolAddress((void**)&s,    g_s);
    cudaGetSymbolAddress((void**)&ph,   g_ph);
    cudaGetSymbolAddress((void**)&ctxh, g_ctxh);
    cudaGetSymbolAddress((void**)&hid,  g_hid);
    cudaGetSymbolAddress((void**)&wqT,  g_wqT);
    cudaGetSymbolAddress((void**)&wkT,  g_wkT);
    cudaGetSymbolAddress((void**)&wvT,  g_wvT);
    cudaGetSymbolAddress((void**)&woT,  g_woT);

    cudaFuncSetAttribute(gemm_h_kernel<float>,  cudaFuncAttributeMaxDynamicSharedMemorySize, GEMM_SMEM);
    cudaFuncSetAttribute(gemm_h_kernel<__half>, cudaFuncAttributeMaxDynamicSharedMemorySize, GEMM_SMEM);

    const dim3 blk(256);
    const dim3 tblk(32, 8);

    // 0) convert x -> fp16, transpose+convert weights -> fp16
    convert_f32_f16_kernel<<<(NROWS * DMODEL / 4 + 255) / 256, 256>>>(
        (const float4*)x, (uint2*)xh, NROWS * DMODEL / 4);
    {
        dim3 tg(DMODEL / 32, DMODEL / 32);
        transpose_w_kernel<<<tg, tblk>>>(Wq, wqT, DMODEL, DMODEL);
        transpose_w_kernel<<<tg, tblk>>>(Wk, wkT, DMODEL, DMODEL);
        transpose_w_kernel<<<tg, tblk>>>(Wv, wvT, DMODEL, DMODEL);
        transpose_w_kernel<<<tg, tblk>>>(Wo, woT, DMODEL, DMODEL);
    }

    // 1) projections (fp16 out)
    {
        dim3 grid(DMODEL / 128, NROWS / 128, 1);
        gemm_h_kernel<__half><<<grid, blk, GEMM_SMEM>>>(xh, wqT, qh, DMODEL, DMODEL, DMODEL, DMODEL, 0, 0, 0, 1.0f);
        gemm_h_kernel<__half><<<grid, blk, GEMM_SMEM>>>(xh, wkT, kh, DMODEL, DMODEL, DMODEL, DMODEL, 0, 0, 0, 1.0f);
        gemm_h_kernel<__half><<<grid, blk, GEMM_SMEM>>>(xh, wvT, vh, DMODEL, DMODEL, DMODEL, DMODEL, 0, 0, 0, 1.0f);
    }

    // 2) scores (fp32 out) = q @ k^T / 32
    {
        dim3 grid(SEQ / 128, SEQ / 128, BATCH);
        gemm_h_kernel<float><<<grid, blk, GEMM_SMEM>>>(qh, kh, s, DMODEL, DMODEL, DMODEL, SEQ,
                                                       (long)SEQ * DMODEL, (long)SEQ * DMODEL,
                                                       (long)SEQ * SEQ, 1.0f / 32.0f);
    }

    // 3) softmax -> fp16 probs
    softmax_kernel<<<BATCH * SEQ, blk>>>(s, ph);

    // 4) v^T then ctx = attn @ v (fp16 out)
    {
        dim3 tg(DMODEL / 32, NROWS / 32);
        transpose_h_kernel<<<tg, tblk>>>(vh, vTh, NROWS, DMODEL);
    }
    {
        dim3 grid(DMODEL / 128, SEQ / 128, BATCH);
        gemm_h_kernel<__half><<<grid, blk, GEMM_SMEM>>>(ph, vTh, ctxh, SEQ,
                                                        SEQ, NROWS, DMODEL,
                                                        (long)SEQ * SEQ, (long)SEQ,
                                                        (long)SEQ * DMODEL, 1.0f);
    }

    // 5) hidden (fp32 out) = ctx @ Wo
    {
        dim3 grid(DMODEL / 128, NROWS / 128, 1);
        gemm_h_kernel<float><<<grid, blk, GEMM_SMEM>>>(ctxh, woT, hid, DMODEL, DMODEL, DMODEL, DMODEL, 0, 0, 0, 1.0f);
    }

    // 6) layernorm -> out
    layernorm_kernel<<<NROWS, blk>>>(hid, gamma, beta, out);
}

// round 5
// speedup vs baseline: 7.8942x; 1.1715x over previous
#include <cuda_runtime.h>
#include <cuda_fp16.h>
#include <cstdint>
#include <math.h>

// ---------------------------------------------------------------- problem dims
#define BATCH 4
#define SEQ   2048
#define DMODEL 1024
#define NROWS (BATCH * SEQ)   // 8192

// ---------------------------------------------------------------- scratch
__device__ __half g_xh  [NROWS * DMODEL];
__device__ __half g_qkv [NROWS * 3 * DMODEL];    // [8192, 3072]: q | k | v
__device__ __half g_vTh [DMODEL * NROWS];        // [1024, 8192]
__device__ __half g_ph  [BATCH * SEQ * SEQ];     // fp16 scores -> probs (in-place)
__device__ __half g_ctxh[NROWS * DMODEL];
__device__ float  g_hid [NROWS * DMODEL];
__device__ __half g_wT  [3 * DMODEL * DMODEL];   // WqT | WkT | WvT
__device__ __half g_woT [DMODEL * DMODEL];

// ---------------------------------------------------------------- helpers
__device__ __forceinline__ uint32_t smem_u32(const void* p) {
    uint32_t a;
    asm("{ .reg .u64 t; cvta.to.shared.u64 t, %1; cvt.u32.u64 %0, t; }" : "=r"(a) : "l"(p));
    return a;
}
__device__ __forceinline__ void cp_async16(uint32_t dst, const void* src) {
    asm volatile("cp.async.cg.shared.global [%0], [%1], 16;" :: "r"(dst), "l"(src) : "memory");
}
#define CP_COMMIT() asm volatile("cp.async.commit_group;" ::: "memory")
#define CP_WAIT1()  asm volatile("cp.async.wait_group 1;" ::: "memory")

__device__ __forceinline__ void ldsm_x4(uint32_t& r0, uint32_t& r1, uint32_t& r2, uint32_t& r3,
                                        uint32_t addr) {
    asm volatile("ldmatrix.sync.aligned.m8n8.x4.shared.b16 {%0,%1,%2,%3}, [%4];"
                 : "=r"(r0), "=r"(r1), "=r"(r2), "=r"(r3) : "r"(addr));
}
__device__ __forceinline__ void mma_f16(float* d, uint32_t a0, uint32_t a1, uint32_t a2, uint32_t a3,
                                        uint32_t b0, uint32_t b1) {
    asm volatile("mma.sync.aligned.m16n8k16.row.col.f32.f16.f16.f32 "
                 "{%0,%1,%2,%3},{%4,%5,%6,%7},{%8,%9},{%0,%1,%2,%3};"
                 : "+f"(d[0]), "+f"(d[1]), "+f"(d[2]), "+f"(d[3])
                 : "r"(a0), "r"(a1), "r"(a2), "r"(a3), "r"(b0), "r"(b1));
}

// ---------------------------------------------------------------- GEMM
// C[M,N] = alpha * A[M,K] @ B[N,K]^T, A,B fp16 K-major. Tile 128x128x64, 3 stages.
// smem row: 128B payload (64 fp16) + 16B pad = 144B stride (conflict-free ldmatrix:
// 144 mod 128 = 16 -> 8 consecutive rows hit 8 distinct 16B offsets).
#define ROW_B   144u
#define HALF_B  18432u          // 128 * 144
#define STAGE_B 36864u
#define NSTAGE  3
#define GEMM_SMEM (NSTAGE * STAGE_B)   // 110592

template<typename OT>
__global__ __launch_bounds__(256, 2)
void gemm_h_kernel(const __half* __restrict__ A, const __half* __restrict__ B,
                   OT* __restrict__ C,
                   int K, int lda, int ldb, int ldc,
                   long bA, long bB, long bC, float alpha)
{
    extern __shared__ char smem[];
    const uint32_t sbase = smem_u32(smem);
    const int tid = threadIdx.x;
    const int wid = tid >> 5;
    const int lane = tid & 31;

    A += blockIdx.z * bA; B += blockIdx.z * bB; C += blockIdx.z * bC;
    const int bm = blockIdx.y * 128;
    const int bn = blockIdx.x * 128;
    const __half* Ab = A + (long)bm * lda;
    const __half* Bb = B + (long)bn * ldb;

    const int wm = (wid & 1) * 64;
    const int wn = (wid >> 1) * 32;

    float acc[4][4][4];
    #pragma unroll
    for (int i = 0; i < 4; i++)
        #pragma unroll
        for (int j = 0; j < 4; j++)
            #pragma unroll
            for (int f = 0; f < 4; f++) acc[i][j][f] = 0.f;

    // ldmatrix per-lane address components
    const uint32_t a_row = (uint32_t)(wm + (lane & 15));
    const uint32_t a_col = (uint32_t)((lane >> 4) * 16);
    const uint32_t b_row = (uint32_t)(wn + (lane & 7) + ((lane >> 4) & 1) * 8);
    const uint32_t b_col = (uint32_t)(((lane >> 3) & 1) * 16);

    // cp.async mapping: 1024 chunks (16B) per operand per stage; 4 per thread per operand
    const int row0 = tid >> 3;           // 0..31
    const int jj   = tid & 7;            // chunk within row

    const int NK = K >> 6;

    // prologue: stages 0,1
    #pragma unroll
    for (int s = 0; s < 2; s++) {
        if (s < NK) {
            const int kt = s * 64;
            const uint32_t sa = sbase + (uint32_t)s * STAGE_B;
            const uint32_t sb = sa + HALF_B;
            #pragma unroll
            for (int i = 0; i < 4; i++) {
                const int r = row0 + i * 32;
                cp_async16(sa + r * ROW_B + jj * 16u, Ab + (long)r * lda + kt + jj * 8);
                cp_async16(sb + r * ROW_B + jj * 16u, Bb + (long)r * ldb + kt + jj * 8);
            }
        }
        CP_COMMIT();
    }

    int rs = 0;   // read stage
    #pragma unroll 1
    for (int it = 0; it < NK; it++) {
        CP_WAIT1();
        __syncthreads();

        const uint32_t sa = sbase + (uint32_t)rs * STAGE_B;
        const uint32_t sb = sa + HALF_B;

        #pragma unroll
        for (int ks = 0; ks < 4; ks++) {
            uint32_t a[4][4];
            #pragma unroll
            for (int mt = 0; mt < 4; mt++) {
                uint32_t addr = sa + (a_row + (uint32_t)(mt * 16)) * ROW_B
                              + a_col + (uint32_t)(ks * 32);
                ldsm_x4(a[mt][0], a[mt][1], a[mt][2], a[mt][3], addr);
            }
            uint32_t b[4][2];
            #pragma unroll
            for (int nb = 0; nb < 2; nb++) {
                uint32_t t0, t1, t2, t3;
                uint32_t addr = sb + (b_row + (uint32_t)(nb * 16)) * ROW_B
                              + b_col + (uint32_t)(ks * 32);
                ldsm_x4(t0, t1, t2, t3, addr);
                b[2 * nb][0] = t0; b[2 * nb][1] = t1;
                b[2 * nb + 1][0] = t2; b[2 * nb + 1][1] = t3;
            }
            #pragma unroll
            for (int mt = 0; mt < 4; mt++)
                #pragma unroll
                for (int nt = 0; nt < 4; nt++)
                    mma_f16(acc[mt][nt], a[mt][0], a[mt][1], a[mt][2], a[mt][3],
                            b[nt][0], b[nt][1]);
        }

        const int sn = it + 2;
        if (sn < NK) {
            const int kt = sn * 64;
            int ws = rs + 2; if (ws >= NSTAGE) ws -= NSTAGE;
            const uint32_t sa2 = sbase + (uint32_t)ws * STAGE_B;
            const uint32_t sb2 = sa2 + HALF_B;
            #pragma unroll
            for (int i = 0; i < 4; i++) {
                const int r = row0 + i * 32;
                cp_async16(sa2 + r * ROW_B + jj * 16u, Ab + (long)r * lda + kt + jj * 8);
                cp_async16(sb2 + r * ROW_B + jj * 16u, Bb + (long)r * ldb + kt + jj * 8);
            }
        }
        CP_COMMIT();

        if (++rs == NSTAGE) rs = 0;
    }

    // epilogue
    const int er = lane >> 2;
    const int ec = (lane & 3) * 2;
    #pragma unroll
    for (int mt = 0; mt < 4; mt++) {
        #pragma unroll
        for (int nt = 0; nt < 4; nt++) {
            const int row = bm + wm + mt * 16 + er;
            const int col = bn + wn + nt * 8 + ec;
            float v0 = acc[mt][nt][0] * alpha, v1 = acc[mt][nt][1] * alpha;
            float v2 = acc[mt][nt][2] * alpha, v3 = acc[mt][nt][3] * alpha;
            if constexpr (sizeof(OT) == 2) {
                *reinterpret_cast<__half2*>((__half*)C + (long)row * ldc + col) =
                    __floats2half2_rn(v0, v1);
                *reinterpret_cast<__half2*>((__half*)C + (long)(row + 8) * ldc + col) =
                    __floats2half2_rn(v2, v3);
            } else {
                *reinterpret_cast<float2*>((float*)C + (long)row * ldc + col) =
                    make_float2(v0, v1);
                *reinterpret_cast<float2*>((float*)C + (long)(row + 8) * ldc + col) =
                    make_float2(v2, v3);
            }
        }
    }
}

// ---------------------------------------------------------------- aux kernels
__global__ void convert_f32_f16_kernel(const float4* __restrict__ in, uint2* __restrict__ out, int n4)
{
    int i = blockIdx.x * blockDim.x + threadIdx.x;
    if (i < n4) {
        float4 v = in[i];
        __half2 lo = __floats2half2_rn(v.x, v.y);
        __half2 hi = __floats2half2_rn(v.z, v.w);
        uint2 o;
        o.x = *reinterpret_cast<uint32_t*>(&lo);
        o.y = *reinterpret_cast<uint32_t*>(&hi);
        out[i] = o;
    }
}

// out[C,R] (fp16) = in[R,C]^T (fp32)
__global__ void transpose_w_kernel(const float* __restrict__ in, __half* __restrict__ out, int R, int C)
{
    __shared__ float t[32][33];
    const int cb = blockIdx.x * 32, rb = blockIdx.y * 32;
    const int x = threadIdx.x, y = threadIdx.y;   // 32 x 8
    #pragma unroll
    for (int i = 0; i < 32; i += 8)
        t[y + i][x] = in[(long)(rb + y + i) * C + cb + x];
    __syncthreads();
    #pragma unroll
    for (int i = 0; i < 32; i += 8)
        out[(long)(cb + y + i) * R + rb + x] = __float2half(t[x][y + i]);
}

// out[C rows, R cols] (fp16) = in[R, C]^T (fp16), in has row stride lda, out stride R
__global__ void transpose_h_kernel(const __half* __restrict__ in, __half* __restrict__ out,
                                   int R, int C, int lda)
{
    __shared__ __half t[32][34];
    const int cb = blockIdx.x * 32, rb = blockIdx.y * 32;
    const int x = threadIdx.x, y = threadIdx.y;   // 32 x 8
    #pragma unroll
    for (int i = 0; i < 32; i += 8)
        t[y + i][x] = in[(long)(rb + y + i) * lda + cb + x];
    __syncthreads();
    #pragma unroll
    for (int i = 0; i < 32; i += 8)
        out[(long)(cb + y + i) * R + rb + x] = t[x][y + i];
}

// in-place softmax over rows of 2048 fp16
__global__ __launch_bounds__(256)
void softmax_h_kernel(__half* __restrict__ p)
{
    __shared__ float sm[8];
    const long row = blockIdx.x;
    __half* r = p + row * (long)SEQ;
    const int tid = threadIdx.x;

    uint2 u0 = reinterpret_cast<const uint2*>(r)[tid];
    uint2 u1 = reinterpret_cast<const uint2*>(r)[tid + 256];
    float2 f0 = __half22float2(*reinterpret_cast<__half2*>(&u0.x));
    float2 f1 = __half22float2(*reinterpret_cast<__half2*>(&u0.y));
    float2 f2 = __half22float2(*reinterpret_cast<__half2*>(&u1.x));
    float2 f3 = __half22float2(*reinterpret_cast<__half2*>(&u1.y));

    float m = fmaxf(fmaxf(fmaxf(f0.x, f0.y), fmaxf(f1.x, f1.y)),
                    fmaxf(fmaxf(f2.x, f2.y), fmaxf(f3.x, f3.y)));
    #pragma unroll
    for (int of = 16; of; of >>= 1) m = fmaxf(m, __shfl_xor_sync(0xffffffffu, m, of));
    if ((tid & 31) == 0) sm[tid >> 5] = m;
    __syncthreads();
    if (tid == 0) {
        float mm = sm[0];
        #pragma unroll
        for (int i = 1; i < 8; i++) mm = fmaxf(mm, sm[i]);
        sm[0] = mm;
    }
    __syncthreads();
    m = sm[0];
    __syncthreads();

    f0.x = __expf(f0.x - m); f0.y = __expf(f0.y - m);
    f1.x = __expf(f1.x - m); f1.y = __expf(f1.y - m);
    f2.x = __expf(f2.x - m); f2.y = __expf(f2.y - m);
    f3.x = __expf(f3.x - m); f3.y = __expf(f3.y - m);

    float su = f0.x + f0.y + f1.x + f1.y + f2.x + f2.y + f3.x + f3.y;
    #pragma unroll
    for (int of = 16; of; of >>= 1) su += __shfl_xor_sync(0xffffffffu, su, of);
    if ((tid & 31) == 0) sm[tid >> 5] = su;
    __syncthreads();
    if (tid == 0) {
        float ss = 0.f;
        #pragma unroll
        for (int i = 0; i < 8; i++) ss += sm[i];
        sm[0] = ss;
    }
    __syncthreads();
    const float inv = 1.0f / sm[0];

    __half2 h0 = __floats2half2_rn(f0.x * inv, f0.y * inv);
    __half2 h1 = __floats2half2_rn(f1.x * inv, f1.y * inv);
    __half2 h2 = __floats2half2_rn(f2.x * inv, f2.y * inv);
    __half2 h3 = __floats2half2_rn(f3.x * inv, f3.y * inv);
    uint2 o0, o1;
    o0.x = *reinterpret_cast<uint32_t*>(&h0);
    o0.y = *reinterpret_cast<uint32_t*>(&h1);
    o1.x = *reinterpret_cast<uint32_t*>(&h2);
    o1.y = *reinterpret_cast<uint32_t*>(&h3);
    reinterpret_cast<uint2*>(r)[tid]       = o0;
    reinterpret_cast<uint2*>(r)[tid + 256] = o1;
}

__global__ __launch_bounds__(256)
void layernorm_kernel(const float* __restrict__ h,
                      const float* __restrict__ gamma,
                      const float* __restrict__ beta,
                      float* __restrict__ out)
{
    __shared__ float sm[8];
    const long row = blockIdx.x;
    const int tid = threadIdx.x;
    const float* r = h + row * (long)DMODEL;

    float4 v = *reinterpret_cast<const float4*>(r + tid * 4);

    float s = v.x + v.y + v.z + v.w;
    #pragma unroll
    for (int o = 16; o; o >>= 1) s += __shfl_xor_sync(0xffffffffu, s, o);
    if ((tid & 31) == 0) sm[tid >> 5] = s;
    __syncthreads();
    if (tid == 0) {
        float ss = 0.f;
        #pragma unroll
        for (int i = 0; i < 8; i++) ss += sm[i];
        sm[0] = ss;
    }
    __syncthreads();
    const float mu = sm[0] * (1.0f / DMODEL);
    __syncthreads();

    float dx = v.x - mu, dy = v.y - mu, dz = v.z - mu, dw = v.w - mu;
    float sq = dx * dx + dy * dy + dz * dz + dw * dw;
    #pragma unroll
    for (int o = 16; o; o >>= 1) sq += __shfl_xor_sync(0xffffffffu, sq, o);
    if ((tid & 31) == 0) sm[tid >> 5] = sq;
    __syncthreads();
    if (tid == 0) {
        float ss = 0.f;
        #pragma unroll
        for (int i = 0; i < 8; i++) ss += sm[i];
        sm[0] = ss;
    }
    __syncthreads();
    const float rstd = rsqrtf(sm[0] * (1.0f / DMODEL) + 1e-5f);

    float4 g = *reinterpret_cast<const float4*>(gamma + tid * 4);
    float4 b = *reinterpret_cast<const float4*>(beta + tid * 4);
    float4 o;
    o.x = dx * rstd * g.x + b.x;
    o.y = dy * rstd * g.y + b.y;
    o.z = dz * rstd * g.z + b.z;
    o.w = dw * rstd * g.w + b.w;
    *reinterpret_cast<float4*>(out + row * (long)DMODEL + tid * 4) = o;
}

// ---------------------------------------------------------------- launch
extern "C" void kernel_launch(void* const* d_in, const int* in_sizes, int n_in,
                              void* d_out, int out_size)
{
    const float* x     = (const float*)d_in[0];
    const float* Wq    = (const float*)d_in[1];
    const float* Wk    = (const float*)d_in[2];
    const float* Wv    = (const float*)d_in[3];
    const float* Wo    = (const float*)d_in[4];
    const float* gamma = (const float*)d_in[5];
    const float* beta  = (const float*)d_in[6];
    float* out = (float*)d_out;

    __half *xh, *qkv, *vTh, *ph, *ctxh, *wT, *woT;
    float *hid;
    cudaGetSymbolAddress((void**)&xh,   g_xh);
    cudaGetSymbolAddress((void**)&qkv,  g_qkv);
    cudaGetSymbolAddress((void**)&vTh,  g_vTh);
    cudaGetSymbolAddress((void**)&ph,   g_ph);
    cudaGetSymbolAddress((void**)&ctxh, g_ctxh);
    cudaGetSymbolAddress((void**)&hid,  g_hid);
    cudaGetSymbolAddress((void**)&wT,   g_wT);
    cudaGetSymbolAddress((void**)&woT,  g_woT);

    cudaFuncSetAttribute(gemm_h_kernel<float>,  cudaFuncAttributeMaxDynamicSharedMemorySize, GEMM_SMEM);
    cudaFuncSetAttribute(gemm_h_kernel<__half>, cudaFuncAttributeMaxDynamicSharedMemorySize, GEMM_SMEM);

    const dim3 blk(256);
    const dim3 tblk(32, 8);

    // 0) convert x -> fp16; transpose+convert weights -> fp16 (QKV into one buffer)
    convert_f32_f16_kernel<<<(NROWS * DMODEL / 4 + 255) / 256, 256>>>(
        (const float4*)x, (uint2*)xh, NROWS * DMODEL / 4);
    {
        dim3 tg(DMODEL / 32, DMODEL / 32);
        transpose_w_kernel<<<tg, tblk>>>(Wq, wT,                       DMODEL, DMODEL);
        transpose_w_kernel<<<tg, tblk>>>(Wk, wT + DMODEL * DMODEL,     DMODEL, DMODEL);
        transpose_w_kernel<<<tg, tblk>>>(Wv, wT + 2 * DMODEL * DMODEL, DMODEL, DMODEL);
        transpose_w_kernel<<<tg, tblk>>>(Wo, woT,                      DMODEL, DMODEL);
    }

    // 1) fused QKV projection: [8192,1024] @ [1024,3072] -> qkv [8192,3072]
    {
        dim3 grid(3 * DMODEL / 128, NROWS / 128, 1);
        gemm_h_kernel<__half><<<grid, blk, GEMM_SMEM>>>(xh, wT, qkv,
                                                        DMODEL, DMODEL, DMODEL, 3 * DMODEL,
                                                        0, 0, 0, 1.0f);
    }

    // 2) scores (fp16) = q @ k^T / 32
    {
        dim3 grid(SEQ / 128, SEQ / 128, BATCH);
        gemm_h_kernel<__half><<<grid, blk, GEMM_SMEM>>>(qkv, qkv + DMODEL, ph,
                                                        DMODEL, 3 * DMODEL, 3 * DMODEL, SEQ,
                                                        (long)SEQ * 3 * DMODEL, (long)SEQ * 3 * DMODEL,
                                                        (long)SEQ * SEQ, 1.0f / 32.0f);
    }

    // 3) in-place softmax -> fp16 probs
    softmax_h_kernel<<<BATCH * SEQ, blk>>>(ph);

    // 4) v^T then ctx = attn @ v (fp16 out)
    {
        dim3 tg(DMODEL / 32, NROWS / 32);
        transpose_h_kernel<<<tg, tblk>>>(qkv + 2 * DMODEL, vTh, NROWS, DMODEL, 3 * DMODEL);
    }
    {
        dim3 grid(DMODEL / 128, SEQ / 128, BATCH);
        gemm_h_kernel<__half><<<grid, blk, GEMM_SMEM>>>(ph, vTh, ctxh, SEQ,
                                                        SEQ, NROWS, DMODEL,
                                                        (long)SEQ * SEQ, (long)SEQ,
                                                        (long)SEQ * DMODEL, 1.0f);
    }

    // 5) hidden (fp32) = ctx @ Wo
    {
        dim3 grid(DMODEL / 128, NROWS / 128, 1);
        gemm_h_kernel<float><<<grid, blk, GEMM_SMEM>>>(ctxh, woT, hid,
                                                       DMODEL, DMODEL, DMODEL, DMODEL, 0, 0, 0, 1.0f);
    }

    // 6) layernorm -> out
    layernorm_kernel<<<NROWS, blk>>>(hid, gamma, beta, out);
}

// round 6
// speedup vs baseline: 8.2344x; 1.0431x over previous
#include <cuda_runtime.h>
#include <cuda_fp16.h>
#include <cstdint>
#include <math.h>

// ---------------------------------------------------------------- problem dims
#define BATCH 4
#define SEQ   2048
#define DMODEL 1024
#define NROWS (BATCH * SEQ)   // 8192

// ---------------------------------------------------------------- scratch
__device__ __half g_xh  [NROWS * DMODEL];
__device__ __half g_qkv [NROWS * 3 * DMODEL];    // [8192, 3072]: q | k | v
__device__ __half g_ph  [BATCH * SEQ * SEQ];     // fp16 exp(scores)
__device__ __half g_ctxh[NROWS * DMODEL];
__device__ float  g_hid [NROWS * DMODEL];
__device__ __half g_whf [DMODEL * 3 * DMODEL];   // [1024, 3072] = Wq|Wk|Wv cols (fp16)
__device__ __half g_woh [DMODEL * DMODEL];       // Wo fp16, [V, D] row-major
__device__ float  g_rowsum[NROWS];               // per-q-row sum of exp(scores)

// ---------------------------------------------------------------- helpers
__device__ __forceinline__ uint32_t smem_u32(const void* p) {
    uint32_t a;
    asm("{ .reg .u64 t; cvta.to.shared.u64 t, %1; cvt.u32.u64 %0, t; }" : "=r"(a) : "l"(p));
    return a;
}
__device__ __forceinline__ void cp_async16(uint32_t dst, const void* src) {
    asm volatile("cp.async.cg.shared.global [%0], [%1], 16;" :: "r"(dst), "l"(src) : "memory");
}
#define CP_COMMIT() asm volatile("cp.async.commit_group;" ::: "memory")
#define CP_WAIT1()  asm volatile("cp.async.wait_group 1;" ::: "memory")

__device__ __forceinline__ void ldsm_x4(uint32_t& r0, uint32_t& r1, uint32_t& r2, uint32_t& r3,
                                        uint32_t addr) {
    asm volatile("ldmatrix.sync.aligned.m8n8.x4.shared.b16 {%0,%1,%2,%3}, [%4];"
                 : "=r"(r0), "=r"(r1), "=r"(r2), "=r"(r3) : "r"(addr));
}
__device__ __forceinline__ void ldsm_x4_t(uint32_t& r0, uint32_t& r1, uint32_t& r2, uint32_t& r3,
                                          uint32_t addr) {
    asm volatile("ldmatrix.sync.aligned.m8n8.x4.trans.shared.b16 {%0,%1,%2,%3}, [%4];"
                 : "=r"(r0), "=r"(r1), "=r"(r2), "=r"(r3) : "r"(addr));
}
__device__ __forceinline__ void mma_f16(float* d, uint32_t a0, uint32_t a1, uint32_t a2, uint32_t a3,
                                        uint32_t b0, uint32_t b1) {
    asm volatile("mma.sync.aligned.m16n8k16.row.col.f32.f16.f16.f32 "
                 "{%0,%1,%2,%3},{%4,%5,%6,%7},{%8,%9},{%0,%1,%2,%3};"
                 : "+f"(d[0]), "+f"(d[1]), "+f"(d[2]), "+f"(d[3])
                 : "r"(a0), "r"(a1), "r"(a2), "r"(a3), "r"(b0), "r"(b1));
}

// ---------------------------------------------------------------- GEMM
// C[M,N] = alpha * A[M,K] @ op(B). A fp16 [M,K] K-major.
//  TRANSB=false: B fp16 [N,K] K-major (C = A@B^T pattern, smem rows = n).
//  TRANSB=true : B fp16 [K,N] N-major (C = A@B,  smem rows = k, ldmatrix.trans).
// Tile 128x128x64, 3 stages.
// A smem row: 128B payload + 16B pad = 144B.   (row = m)
// B smem (!T): 128 rows x 144B.  (row = n)
// B smem (T):  64 rows x 272B (256B payload + 16B pad). (row = k)
#define ROW_A   144u
#define ROW_BT  272u
#define HALF_A  18432u          // 128 * 144
#define STAGE_B 36864u          // A half + B half (B uses <= 18432)
#define NSTAGE  3
#define GEMM_SMEM (NSTAGE * STAGE_B)   // 110592

// MODE: 0 = plain, 1 = exp(alpha*acc) + atomic row sums, 2 = scale rows by 1/rowsum
template<typename OT, bool TRANSB, int MODE>
__global__ __launch_bounds__(256, 2)
void gemm_h_kernel(const __half* __restrict__ A, const __half* __restrict__ B,
                   OT* __restrict__ C,
                   int K, int lda, int ldb, int ldc,
                   long bA, long bB, long bC, float alpha,
                   float* __restrict__ rowsum, int rs_stride)
{
    extern __shared__ char smem[];
    const uint32_t sbase = smem_u32(smem);
    const int tid = threadIdx.x;
    const int wid = tid >> 5;
    const int lane = tid & 31;

    A += blockIdx.z * bA; B += blockIdx.z * bB; C += blockIdx.z * bC;
    const int bm = blockIdx.y * 128;
    const int bn = blockIdx.x * 128;
    const __half* Ab = A + (long)bm * lda;
    const __half* Bb = TRANSB ? (B + bn) : (B + (long)bn * ldb);

    const int wm = (wid & 1) * 64;
    const int wn = (wid >> 1) * 32;

    float acc[4][4][4];
    #pragma unroll
    for (int i = 0; i < 4; i++)
        #pragma unroll
        for (int j = 0; j < 4; j++)
            #pragma unroll
            for (int f = 0; f < 4; f++) acc[i][j][f] = 0.f;

    // ldmatrix lane components
    const uint32_t a_row = (uint32_t)(wm + (lane & 15));
    const uint32_t a_col = (uint32_t)((lane >> 4) * 16);
    // non-trans B (rows = n)
    const uint32_t b_row = (uint32_t)(wn + (lane & 7) + ((lane >> 4) & 1) * 8);
    const uint32_t b_col = (uint32_t)(((lane >> 3) & 1) * 16);
    // trans B (rows = k)
    const uint32_t bt_k = (uint32_t)((lane & 7) + ((lane >> 3) & 1) * 8);
    const uint32_t bt_n = (uint32_t)(wn + ((lane >> 4) & 1) * 8);

    // cp.async A mapping: 128 rows x 8 chunks; 4 per thread
    const int arow0 = tid >> 3;          // 0..31
    const int ajj   = tid & 7;
    // cp.async B-trans mapping: 64 rows x 16 chunks; 4 per thread
    const int NK = K >> 6;

    // ---- stage loader ----
    auto load_stage = [&](int s, int buf) {
        const int kt = s * 64;
        const uint32_t sa = sbase + (uint32_t)buf * STAGE_B;
        const uint32_t sb = sa + HALF_A;
        #pragma unroll
        for (int i = 0; i < 4; i++) {
            const int r = arow0 + i * 32;
            cp_async16(sa + r * ROW_A + ajj * 16u, Ab + (long)r * lda + kt + ajj * 8);
        }
        if constexpr (!TRANSB) {
            #pragma unroll
            for (int i = 0; i < 4; i++) {
                const int r = arow0 + i * 32;
                cp_async16(sb + r * ROW_A + ajj * 16u, Bb + (long)r * ldb + kt + ajj * 8);
            }
        } else {
            #pragma unroll
            for (int i = 0; i < 4; i++) {
                const int idx = i * 256 + tid;
                const int r = idx >> 4;          // 0..63 (k)
                const int j = idx & 15;          // 16B chunk along n
                cp_async16(sb + r * ROW_BT + j * 16u, Bb + (long)(kt + r) * ldb + j * 8);
            }
        }
    };

    // prologue
    #pragma unroll
    for (int s = 0; s < 2; s++) {
        if (s < NK) load_stage(s, s);
        CP_COMMIT();
    }

    int rs = 0;
    #pragma unroll 1
    for (int it = 0; it < NK; it++) {
        CP_WAIT1();
        __syncthreads();

        const uint32_t sa = sbase + (uint32_t)rs * STAGE_B;
        const uint32_t sb = sa + HALF_A;

        #pragma unroll
        for (int ks = 0; ks < 4; ks++) {
            uint32_t a[4][4];
            #pragma unroll
            for (int mt = 0; mt < 4; mt++) {
                uint32_t addr = sa + (a_row + (uint32_t)(mt * 16)) * ROW_A
                              + a_col + (uint32_t)(ks * 32);
                ldsm_x4(a[mt][0], a[mt][1], a[mt][2], a[mt][3], addr);
            }
            uint32_t b[4][2];
            #pragma unroll
            for (int nb = 0; nb < 2; nb++) {
                uint32_t t0, t1, t2, t3;
                if constexpr (!TRANSB) {
                    uint32_t addr = sb + (b_row + (uint32_t)(nb * 16)) * ROW_A
                                  + b_col + (uint32_t)(ks * 32);
                    ldsm_x4(t0, t1, t2, t3, addr);
                } else {
                    uint32_t addr = sb + ((uint32_t)(ks * 16) + bt_k) * ROW_BT
                                  + (bt_n + (uint32_t)(nb * 16)) * 2u;
                    ldsm_x4_t(t0, t1, t2, t3, addr);
                }
                b[2 * nb][0] = t0; b[2 * nb][1] = t1;
                b[2 * nb + 1][0] = t2; b[2 * nb + 1][1] = t3;
            }
            #pragma unroll
            for (int mt = 0; mt < 4; mt++)
                #pragma unroll
                for (int nt = 0; nt < 4; nt++)
                    mma_f16(acc[mt][nt], a[mt][0], a[mt][1], a[mt][2], a[mt][3],
                            b[nt][0], b[nt][1]);
        }

        const int sn = it + 2;
        if (sn < NK) {
            int ws = rs + 2; if (ws >= NSTAGE) ws -= NSTAGE;
            load_stage(sn, ws);
        }
        CP_COMMIT();

        if (++rs == NSTAGE) rs = 0;
    }

    // ---- epilogue ----
    const int er = lane >> 2;
    const int ec = (lane & 3) * 2;
    const int rbase = (MODE != 0) ? blockIdx.z * rs_stride : 0;

    #pragma unroll
    for (int mt = 0; mt < 4; mt++) {
        const int row0 = bm + wm + mt * 16 + er;
        float inv0 = 1.f, inv1 = 1.f;
        if constexpr (MODE == 2) {
            inv0 = 1.0f / rowsum[rbase + row0];
            inv1 = 1.0f / rowsum[rbase + row0 + 8];
        }
        float rsum0 = 0.f, rsum1 = 0.f;
        #pragma unroll
        for (int nt = 0; nt < 4; nt++) {
            const int col = bn + wn + nt * 8 + ec;
            float v0 = acc[mt][nt][0] * alpha, v1 = acc[mt][nt][1] * alpha;
            float v2 = acc[mt][nt][2] * alpha, v3 = acc[mt][nt][3] * alpha;
            if constexpr (MODE == 1) {
                v0 = __expf(v0); v1 = __expf(v1);
                v2 = __expf(v2); v3 = __expf(v3);
                rsum0 += v0 + v1; rsum1 += v2 + v3;
            }
            if constexpr (MODE == 2) {
                v0 *= inv0; v1 *= inv0; v2 *= inv1; v3 *= inv1;
            }
            if constexpr (sizeof(OT) == 2) {
                *reinterpret_cast<__half2*>((__half*)C + (long)row0 * ldc + col) =
                    __floats2half2_rn(v0, v1);
                *reinterpret_cast<__half2*>((__half*)C + (long)(row0 + 8) * ldc + col) =
                    __floats2half2_rn(v2, v3);
            } else {
                *reinterpret_cast<float2*>((float*)C + (long)row0 * ldc + col) =
                    make_float2(v0, v1);
                *reinterpret_cast<float2*>((float*)C + (long)(row0 + 8) * ldc + col) =
                    make_float2(v2, v3);
            }
        }
        if constexpr (MODE == 1) {
            rsum0 += __shfl_xor_sync(0xffffffffu, rsum0, 1);
            rsum0 += __shfl_xor_sync(0xffffffffu, rsum0, 2);
            rsum1 += __shfl_xor_sync(0xffffffffu, rsum1, 1);
            rsum1 += __shfl_xor_sync(0xffffffffu, rsum1, 2);
            if ((lane & 3) == 0) {
                atomicAdd(rowsum + rbase + row0, rsum0);
                atomicAdd(rowsum + rbase + row0 + 8, rsum1);
            }
        }
    }
}

// ---------------------------------------------------------------- aux kernels
__global__ void zero_rowsum_kernel(float* __restrict__ rs)
{
    rs[blockIdx.x * 1024 + threadIdx.x] = 0.f;
}

__global__ void convert_f32_f16_kernel(const float4* __restrict__ in, uint2* __restrict__ out, int n4)
{
    int i = blockIdx.x * blockDim.x + threadIdx.x;
    if (i < n4) {
        float4 v = in[i];
        __half2 lo = __floats2half2_rn(v.x, v.y);
        __half2 hi = __floats2half2_rn(v.z, v.w);
        uint2 o;
        o.x = *reinterpret_cast<uint32_t*>(&lo);
        o.y = *reinterpret_cast<uint32_t*>(&hi);
        out[i] = o;
    }
}

// whf[1024][3072] = [Wq | Wk | Wv] fp16 ; woh[1024][1024] = Wo fp16
__global__ void convert_w_kernel(const float* __restrict__ Wq, const float* __restrict__ Wk,
                                 const float* __restrict__ Wv, const float* __restrict__ Wo,
                                 __half* __restrict__ whf, __half* __restrict__ woh)
{
    const int i = blockIdx.x * blockDim.x + threadIdx.x;   // float4 index, 1M total
    const int e = i * 4;
    const float* src;
    __half* dst;
    if (e < 3 * DMODEL * DMODEL) {
        const int row = e / (3 * DMODEL);
        const int col = e % (3 * DMODEL);
        const int sel = col >> 10;
        const int c   = col & 1023;
        src = (sel == 0 ? Wq : (sel == 1 ? Wk : Wv)) + (long)row * DMODEL + c;
        dst = whf + e;
    } else {
        const int e2 = e - 3 * DMODEL * DMODEL;
        src = Wo + e2;
        dst = woh + e2;
    }
    float4 v = *reinterpret_cast<const float4*>(src);
    __half2 lo = __floats2half2_rn(v.x, v.y);
    __half2 hi = __floats2half2_rn(v.z, v.w);
    uint2 o;
    o.x = *reinterpret_cast<uint32_t*>(&lo);
    o.y = *reinterpret_cast<uint32_t*>(&hi);
    *reinterpret_cast<uint2*>(dst) = o;
}

__global__ __launch_bounds__(256)
void layernorm_kernel(const float* __restrict__ h,
                      const float* __restrict__ gamma,
                      const float* __restrict__ beta,
                      float* __restrict__ out)
{
    __shared__ float sm[8];
    const long row = blockIdx.x;
    const int tid = threadIdx.x;
    const float* r = h + row * (long)DMODEL;

    float4 v = *reinterpret_cast<const float4*>(r + tid * 4);

    float s = v.x + v.y + v.z + v.w;
    #pragma unroll
    for (int o = 16; o; o >>= 1) s += __shfl_xor_sync(0xffffffffu, s, o);
    if ((tid & 31) == 0) sm[tid >> 5] = s;
    __syncthreads();
    if (tid == 0) {
        float ss = 0.f;
        #pragma unroll
        for (int i = 0; i < 8; i++) ss += sm[i];
        sm[0] = ss;
    }
    __syncthreads();
    const float mu = sm[0] * (1.0f / DMODEL);
    __syncthreads();

    float dx = v.x - mu, dy = v.y - mu, dz = v.z - mu, dw = v.w - mu;
    float sq = dx * dx + dy * dy + dz * dz + dw * dw;
    #pragma unroll
    for (int o = 16; o; o >>= 1) sq += __shfl_xor_sync(0xffffffffu, sq, o);
    if ((tid & 31) == 0) sm[tid >> 5] = sq;
    __syncthreads();
    if (tid == 0) {
        float ss = 0.f;
        #pragma unroll
        for (int i = 0; i < 8; i++) ss += sm[i];
        sm[0] = ss;
    }
    __syncthreads();
    const float rstd = rsqrtf(sm[0] * (1.0f / DMODEL) + 1e-5f);

    float4 g = *reinterpret_cast<const float4*>(gamma + tid * 4);
    float4 b = *reinterpret_cast<const float4*>(beta + tid * 4);
    float4 o;
    o.x = dx * rstd * g.x + b.x;
    o.y = dy * rstd * g.y + b.y;
    o.z = dz * rstd * g.z + b.z;
    o.w = dw * rstd * g.w + b.w;
    *reinterpret_cast<float4*>(out + row * (long)DMODEL + tid * 4) = o;
}

// ---------------------------------------------------------------- launch
extern "C" void kernel_launch(void* const* d_in, const int* in_sizes, int n_in,
                              void* d_out, int out_size)
{
    const float* x     = (const float*)d_in[0];
    const float* Wq    = (const float*)d_in[1];
    const float* Wk    = (const float*)d_in[2];
    const float* Wv    = (const float*)d_in[3];
    const float* Wo    = (const float*)d_in[4];
    const float* gamma = (const float*)d_in[5];
    const float* beta  = (const float*)d_in[6];
    float* out = (float*)d_out;

    __half *xh, *qkv, *ph, *ctxh, *whf, *woh;
    float *hid, *rowsum;
    cudaGetSymbolAddress((void**)&xh,     g_xh);
    cudaGetSymbolAddress((void**)&qkv,    g_qkv);
    cudaGetSymbolAddress((void**)&ph,     g_ph);
    cudaGetSymbolAddress((void**)&ctxh,   g_ctxh);
    cudaGetSymbolAddress((void**)&hid,    g_hid);
    cudaGetSymbolAddress((void**)&whf,    g_whf);
    cudaGetSymbolAddress((void**)&woh,    g_woh);
    cudaGetSymbolAddress((void**)&rowsum, g_rowsum);

    cudaFuncSetAttribute((const void*)gemm_h_kernel<__half, true,  0>, cudaFuncAttributeMaxDynamicSharedMemorySize, GEMM_SMEM);
    cudaFuncSetAttribute((const void*)gemm_h_kernel<__half, false, 1>, cudaFuncAttributeMaxDynamicSharedMemorySize, GEMM_SMEM);
    cudaFuncSetAttribute((const void*)gemm_h_kernel<__half, true,  2>, cudaFuncAttributeMaxDynamicSharedMemorySize, GEMM_SMEM);
    cudaFuncSetAttribute((const void*)gemm_h_kernel<float,  true,  0>, cudaFuncAttributeMaxDynamicSharedMemorySize, GEMM_SMEM);

    const dim3 blk(256);

    // 0) zero rowsums; convert x and weights to fp16
    zero_rowsum_kernel<<<NROWS / 1024, 1024>>>(rowsum);
    convert_f32_f16_kernel<<<(NROWS * DMODEL / 4 + 255) / 256, 256>>>(
        (const float4*)x, (uint2*)xh, NROWS * DMODEL / 4);
    convert_w_kernel<<<(4 * DMODEL * DMODEL / 4) / 256, 256>>>(Wq, Wk, Wv, Wo, whf, woh);

    // 1) fused QKV projection: [8192,1024] @ whf[1024,3072] -> qkv
    {
        dim3 grid(3 * DMODEL / 128, NROWS / 128, 1);
        gemm_h_kernel<__half, true, 0><<<grid, blk, GEMM_SMEM>>>(
            xh, whf, qkv, DMODEL, DMODEL, 3 * DMODEL, 3 * DMODEL,
            0, 0, 0, 1.0f, nullptr, 0);
    }

    // 2) ph = exp(q @ k^T / 32), rowsum accumulated atomically
    {
        dim3 grid(SEQ / 128, SEQ / 128, BATCH);
        gemm_h_kernel<__half, false, 1><<<grid, blk, GEMM_SMEM>>>(
            qkv, qkv + DMODEL, ph, DMODEL, 3 * DMODEL, 3 * DMODEL, SEQ,
            (long)SEQ * 3 * DMODEL, (long)SEQ * 3 * DMODEL, (long)SEQ * SEQ,
            1.0f / 32.0f, rowsum, SEQ);
    }

    // 3) ctx = (ph @ v) * (1/rowsum)   (v = qkv[:, 2048:3072], [s, d] N-major -> TRANSB)
    {
        dim3 grid(DMODEL / 128, SEQ / 128, BATCH);
        gemm_h_kernel<__half, true, 2><<<grid, blk, GEMM_SMEM>>>(
            ph, qkv + 2 * DMODEL, ctxh, SEQ, SEQ, 3 * DMODEL, DMODEL,
            (long)SEQ * SEQ, (long)SEQ * 3 * DMODEL, (long)SEQ * DMODEL,
            1.0f, rowsum, SEQ);
    }

    // 4) hidden (fp32) = ctx @ woh[1024,1024]
    {
        dim3 grid(DMODEL / 128, NROWS / 128, 1);
        gemm_h_kernel<float, true, 0><<<grid, blk, GEMM_SMEM>>>(
            ctxh, woh, hid, DMODEL, DMODEL, DMODEL, DMODEL,
            0, 0, 0, 1.0f, nullptr, 0);
    }

    // 5) layernorm -> out
    layernorm_kernel<<<NROWS, blk>>>(hid, gamma, beta, out);
}